// round 17
// baseline (speedup 1.0000x reference)
#include <cuda_runtime.h>
#include <cuda_bf16.h>
#include <cstring>

#define BB 4096
#define FF 48
#define AA 6
#define HH 200
#define NG 800
#define RRW 32              // rows per CTA
#define NSTEP 119
#define NTHREADS 800        // 25 warps
#define NCTA (BB / RRW)     // 128

#define ASTR 744            // arena row stride (bf16 elems)

// arena column bases
#define C_INP  0
#define C_H1   56
#define C_TIL  256
#define C_H2   272
#define C_INP2 472
#define C_O3   528

// GEMM shapes
#define KS1 16   // gemm1: A cols 0..255
#define KS2 26   // gemm2: A cols 56..471
#define KS3 16   // fc1:   A cols 272..527
#define KS4 13   // fc2:   A cols 528..735
#define NT1 100
#define NT3 25
#define NT4 6

typedef unsigned int u32;

// ---------------- packed weight fragments: uint4 = {bh0,bh1,bl0,bl1} ----------------
// B1/B2 ntile order: nt = w*4 + g  (warp w owns gates i,f,g,o of units [8w, 8w+8))
__device__ uint4 g_B1[NT1 * KS1 * 32];
__device__ uint4 g_B2[NT1 * KS2 * 32];
__device__ uint4 g_B3[NT3 * KS3 * 32];
__device__ uint4 g_B4[NT4 * KS4 * 32];
__device__ float g_b1[NG];
__device__ float g_b2[NG];

// ---------------- prep ----------------
__device__ __forceinline__ unsigned short bfbits(float v) {
    __nv_bfloat16 b = __float2bfloat16(v);
    unsigned short u; memcpy(&u, &b, 2); return u;
}
__device__ __forceinline__ uint4 packFrag(const float w[4]) {
    unsigned short h[4], l[4];
#pragma unroll
    for (int e = 0; e < 4; e++) {
        __nv_bfloat16 hb = __float2bfloat16(w[e]);
        h[e] = bfbits(w[e]);
        l[e] = bfbits(w[e] - __bfloat162float(hb));
    }
    uint4 r;
    r.x = (u32)h[0] | ((u32)h[1] << 16);
    r.y = (u32)h[2] | ((u32)h[3] << 16);
    r.z = (u32)l[0] | ((u32)l[1] << 16);
    r.w = (u32)l[2] | ((u32)l[3] << 16);
    return r;
}

__global__ void prep_kernel(const float* __restrict__ Wih1, const float* __restrict__ Whh1,
                            const float* __restrict__ bih1, const float* __restrict__ bhh1,
                            const float* __restrict__ Wih2, const float* __restrict__ Whh2,
                            const float* __restrict__ bih2, const float* __restrict__ bhh2,
                            const float* __restrict__ fc1w, const float* __restrict__ fc2w)
{
    int tid = blockIdx.x * blockDim.x + threadIdx.x;
    int stride = gridDim.x * blockDim.x;
    for (int i = tid; i < NG; i += stride) {
        g_b1[i] = bih1[i] + bhh1[i];
        g_b2[i] = bih2[i] + bhh2[i];
    }
    // GEMM1: K-span [inp48 | zp8 | h1 200] = 256, nt = w*4+g
    for (int i = tid; i < NT1 * KS1 * 32; i += stride) {
        int lane = i & 31, ks = (i >> 5) % KS1, nt = i / (32 * KS1);
        int w8 = nt >> 2, g = nt & 3;
        int n = g * 200 + w8 * 8 + (lane >> 2);
        int k0 = ks * 16 + (lane & 3) * 2;
        float w[4];
#pragma unroll
        for (int e = 0; e < 4; e++) {
            int k = k0 + (e >> 1) * 8 + (e & 1);
            float v;
            if (k < 48)       v = Wih1[n * 48 + k];
            else if (k < 56)  v = 0.0f;
            else              v = Whh1[n * 200 + (k - 56)];
            w[e] = v;
        }
        g_B1[i] = packFrag(w);
    }
    // GEMM2: K-span [h1 200 | til_folded 12 | zp4 | h2 200] = 416, nt = w*4+g
    for (int i = tid; i < NT1 * KS2 * 32; i += stride) {
        int lane = i & 31, ks = (i >> 5) % KS2, nt = i / (32 * KS2);
        int w8 = nt >> 2, g = nt & 3;
        int n = g * 200 + w8 * 8 + (lane >> 2);
        int k0 = ks * 16 + (lane & 3) * 2;
        float w[4];
#pragma unroll
        for (int e = 0; e < 4; e++) {
            int k = k0 + (e >> 1) * 8 + (e & 1);
            float v;
            if (k < 200) v = Wih2[n * 248 + k];
            else if (k < 212) {
                v = 0.0f;
#pragma unroll
                for (int r = 0; r < 4; r++) v += Wih2[n * 248 + 200 + (k - 200) + 12 * r];
            }
            else if (k < 216) v = 0.0f;
            else              v = Whh2[n * 200 + (k - 216)];
            w[e] = v;
        }
        g_B2[i] = packFrag(w);
    }
    // fc1: K-span [h2 200 | inp 48 | zp8] = 256, N = 200
    for (int i = tid; i < NT3 * KS3 * 32; i += stride) {
        int lane = i & 31, ks = (i >> 5) % KS3, nt = i / (32 * KS3);
        int n = nt * 8 + (lane >> 2);
        int k0 = ks * 16 + (lane & 3) * 2;
        float w[4];
#pragma unroll
        for (int e = 0; e < 4; e++) {
            int k = k0 + (e >> 1) * 8 + (e & 1);
            w[e] = (k < 248) ? fc1w[n * 248 + k] : 0.0f;
        }
        g_B3[i] = packFrag(w);
    }
    // fc2: K-span [o3 200 | zp8] = 208, N = 48
    for (int i = tid; i < NT4 * KS4 * 32; i += stride) {
        int lane = i & 31, ks = (i >> 5) % KS4, nt = i / (32 * KS4);
        int n = nt * 8 + (lane >> 2);
        int k0 = ks * 16 + (lane & 3) * 2;
        float w[4];
#pragma unroll
        for (int e = 0; e < 4; e++) {
            int k = k0 + (e >> 1) * 8 + (e & 1);
            w[e] = (k < 200) ? fc2w[n * 200 + k] : 0.0f;
        }
        g_B4[i] = packFrag(w);
    }
}

// ---------------- mma primitives ----------------
__device__ __forceinline__ u32 smem_u32(const void* p) {
    return (u32)__cvta_generic_to_shared(p);
}
__device__ __forceinline__ void ldm_x4(u32 a[4], u32 addr) {
    asm volatile("ldmatrix.sync.aligned.m8n8.x4.shared.b16 {%0,%1,%2,%3}, [%4];"
                 : "=r"(a[0]), "=r"(a[1]), "=r"(a[2]), "=r"(a[3]) : "r"(addr));
}
__device__ __forceinline__ void mma_bf16(float c[4], const u32 a[4], u32 b0, u32 b1) {
    asm volatile("mma.sync.aligned.m16n8k16.row.col.f32.bf16.bf16.f32 "
                 "{%0,%1,%2,%3}, {%4,%5,%6,%7}, {%8,%9}, {%0,%1,%2,%3};"
                 : "+f"(c[0]), "+f"(c[1]), "+f"(c[2]), "+f"(c[3])
                 : "r"(a[0]), "r"(a[1]), "r"(a[2]), "r"(a[3]), "r"(b0), "r"(b1));
}
__device__ __forceinline__ float sigm(float x) { return 1.0f / (1.0f + expf(-x)); }

// paired split store: two adjacent columns as one 32-bit store per arena
__device__ __forceinline__ void splitStore2(float v0, float v1,
                                            __nv_bfloat16* hiA, __nv_bfloat16* loA, int idx) {
    __nv_bfloat16 h0 = __float2bfloat16(v0);
    __nv_bfloat16 h1 = __float2bfloat16(v1);
    *(__nv_bfloat162*)&hiA[idx] = __nv_bfloat162(h0, h1);
    *(__nv_bfloat162*)&loA[idx] = __nv_bfloat162(
        __float2bfloat16(v0 - __bfloat162float(h0)),
        __float2bfloat16(v1 - __bfloat162float(h1)));
}
__device__ __forceinline__ void splitStore(float v, __nv_bfloat16* hiA, __nv_bfloat16* loA, int idx) {
    __nv_bfloat16 h = __float2bfloat16(v);
    hiA[idx] = h;
    loA[idx] = __float2bfloat16(v - __bfloat162float(h));
}

// ---------------- main persistent kernel ----------------
__global__ void __launch_bounds__(NTHREADS, 1)
actp_main(const float* __restrict__ tactiles, const float* __restrict__ actions,
          const float* __restrict__ fc1b, const float* __restrict__ fc2b,
          float* __restrict__ out)
{
    extern __shared__ char smemraw[];
    __nv_bfloat16* aHi = (__nv_bfloat16*)smemraw;
    __nv_bfloat16* aLo = aHi + RRW * ASTR;
    float* sc1 = (float*)(smemraw + 2 * RRW * ASTR * 2);   // c-state layer1 [row*HH+u]
    float* sc2 = sc1 + RRW * HH;                            // c-state layer2

    const int tid  = threadIdx.x;
    const int lane = tid & 31;
    const int warp = tid >> 5;         // 0..24 = unit-tile
    const int row0 = blockIdx.x * RRW;

    // zero arena + c-state
    {
        u32* z = (u32*)smemraw;
        int nz = (2 * RRW * ASTR * 2) / 4 + 2 * RRW * HH;
        for (int i = tid; i < nz; i += NTHREADS) z[i] = 0;
    }
    __syncthreads();

    // prologue staging
    for (int idx = tid; idx < RRW * FF; idx += NTHREADS) {
        int r = idx / FF, c = idx % FF;
        float v = tactiles[((size_t)0 * BB + row0 + r) * FF + c];
        splitStore(v, aHi, aLo, r * ASTR + C_INP + c);
        splitStore(v, aHi, aLo, r * ASTR + C_INP2 + c);
    }
    for (int idx = tid; idx < RRW * 12; idx += NTHREADS) {
        int r = idx / 12, c = idx % 12;
        float v = (c < 6)
            ? actions[((size_t)1 * BB + row0 + r) * AA + c]
            : actions[(size_t)(row0 + r) * AA + (c - 6)];
        splitStore(v, aHi, aLo, r * ASTR + C_TIL + c);
    }
    __syncthreads();

    // ldmatrix lane geometry (two mtiles: rows +0 and +16)
    const int mq   = lane >> 3;
    const int ldr  = (mq & 1) * 8 + (lane & 7);
    const int ldc  = (mq >> 1) * 8;
    const u32 aHiB0 = smem_u32(aHi) + (u32)(ldr * ASTR + ldc) * 2;
    const u32 aLoB0 = smem_u32(aLo) + (u32)(ldr * ASTR + ldc) * 2;
    const u32 aHiB1 = aHiB0 + (u32)(16 * ASTR) * 2;
    const u32 aLoB1 = aLoB0 + (u32)(16 * ASTR) * 2;
    const int crow = lane >> 2;           // C fragment row
    const int ccol = (lane & 3) * 2;      // C fragment col base
    const int ucol = warp * 8 + ccol;     // this thread's unit pair base

    for (int t = 0; t < NSTEP; t++) {
        // ===== Phase A: GEMM1 (4 gate tiles x 2 mtiles per warp) =====
        float C1[4][2][4];
#pragma unroll
        for (int g = 0; g < 4; g++)
#pragma unroll
            for (int m = 0; m < 2; m++)
#pragma unroll
                for (int e = 0; e < 4; e++) C1[g][m][e] = 0.0f;
#pragma unroll 1
        for (int ks = 0; ks < KS1; ks++) {
            u32 Ah0[4], Al0[4], Ah1[4], Al1[4];
            ldm_x4(Ah0, aHiB0 + (u32)(C_INP * 2 + ks * 32));
            ldm_x4(Al0, aLoB0 + (u32)(C_INP * 2 + ks * 32));
            ldm_x4(Ah1, aHiB1 + (u32)(C_INP * 2 + ks * 32));
            ldm_x4(Al1, aLoB1 + (u32)(C_INP * 2 + ks * 32));
#pragma unroll
            for (int g = 0; g < 4; g++) {
                uint4 b = __ldg(&g_B1[((warp * 4 + g) * KS1 + ks) * 32 + lane]);
                mma_bf16(C1[g][0], Ah0, b.x, b.y);
                mma_bf16(C1[g][0], Ah0, b.z, b.w);
                mma_bf16(C1[g][0], Al0, b.x, b.y);
                mma_bf16(C1[g][1], Ah1, b.x, b.y);
                mma_bf16(C1[g][1], Ah1, b.z, b.w);
                mma_bf16(C1[g][1], Al1, b.x, b.y);
            }
        }
        __syncthreads();   // all GEMM1 reads of h1 done before h1 overwrite

        // ===== Phase B: LSTM1 cell update (registers) -> h1 =====
        {
            float bi0 = __ldg(&g_b1[ucol]),       bi1 = __ldg(&g_b1[ucol + 1]);
            float bf0 = __ldg(&g_b1[200 + ucol]), bf1 = __ldg(&g_b1[201 + ucol]);
            float bg0 = __ldg(&g_b1[400 + ucol]), bg1 = __ldg(&g_b1[401 + ucol]);
            float bo0 = __ldg(&g_b1[600 + ucol]), bo1 = __ldg(&g_b1[601 + ucol]);
#pragma unroll
            for (int m = 0; m < 2; m++)
#pragma unroll
                for (int e2 = 0; e2 < 2; e2++) {
                    int row = crow + 8 * e2 + 16 * m;
                    int e = e2 * 2;
                    float c0 = sigm(C1[1][m][e]   + bf0) * sc1[row * HH + ucol]
                             + sigm(C1[0][m][e]   + bi0) * tanhf(C1[2][m][e]   + bg0);
                    float c1 = sigm(C1[1][m][e+1] + bf1) * sc1[row * HH + ucol + 1]
                             + sigm(C1[0][m][e+1] + bi1) * tanhf(C1[2][m][e+1] + bg1);
                    sc1[row * HH + ucol]     = c0;
                    sc1[row * HH + ucol + 1] = c1;
                    float h0 = sigm(C1[3][m][e]   + bo0) * tanhf(c0);
                    float h1 = sigm(C1[3][m][e+1] + bo1) * tanhf(c1);
                    splitStore2(h0, h1, aHi, aLo, row * ASTR + C_H1 + ucol);
                }
        }
        __syncthreads();

        // ===== Phase C: GEMM2 =====
        float C2g[4][2][4];
#pragma unroll
        for (int g = 0; g < 4; g++)
#pragma unroll
            for (int m = 0; m < 2; m++)
#pragma unroll
                for (int e = 0; e < 4; e++) C2g[g][m][e] = 0.0f;
#pragma unroll 1
        for (int ks = 0; ks < KS2; ks++) {
            u32 Ah0[4], Al0[4], Ah1[4], Al1[4];
            ldm_x4(Ah0, aHiB0 + (u32)(C_H1 * 2 + ks * 32));
            ldm_x4(Al0, aLoB0 + (u32)(C_H1 * 2 + ks * 32));
            ldm_x4(Ah1, aHiB1 + (u32)(C_H1 * 2 + ks * 32));
            ldm_x4(Al1, aLoB1 + (u32)(C_H1 * 2 + ks * 32));
#pragma unroll
            for (int g = 0; g < 4; g++) {
                uint4 b = __ldg(&g_B2[((warp * 4 + g) * KS2 + ks) * 32 + lane]);
                mma_bf16(C2g[g][0], Ah0, b.x, b.y);
                mma_bf16(C2g[g][0], Ah0, b.z, b.w);
                mma_bf16(C2g[g][0], Al0, b.x, b.y);
                mma_bf16(C2g[g][1], Ah1, b.x, b.y);
                mma_bf16(C2g[g][1], Ah1, b.z, b.w);
                mma_bf16(C2g[g][1], Al1, b.x, b.y);
            }
        }
        __syncthreads();   // GEMM2 reads of h2 done before h2 overwrite

        // ===== Phase D: LSTM2 cell update -> h2 =====
        {
            float bi0 = __ldg(&g_b2[ucol]),       bi1 = __ldg(&g_b2[ucol + 1]);
            float bf0 = __ldg(&g_b2[200 + ucol]), bf1 = __ldg(&g_b2[201 + ucol]);
            float bg0 = __ldg(&g_b2[400 + ucol]), bg1 = __ldg(&g_b2[401 + ucol]);
            float bo0 = __ldg(&g_b2[600 + ucol]), bo1 = __ldg(&g_b2[601 + ucol]);
#pragma unroll
            for (int m = 0; m < 2; m++)
#pragma unroll
                for (int e2 = 0; e2 < 2; e2++) {
                    int row = crow + 8 * e2 + 16 * m;
                    int e = e2 * 2;
                    float c0 = sigm(C2g[1][m][e]   + bf0) * sc2[row * HH + ucol]
                             + sigm(C2g[0][m][e]   + bi0) * tanhf(C2g[2][m][e]   + bg0);
                    float c1 = sigm(C2g[1][m][e+1] + bf1) * sc2[row * HH + ucol + 1]
                             + sigm(C2g[0][m][e+1] + bi1) * tanhf(C2g[2][m][e+1] + bg1);
                    sc2[row * HH + ucol]     = c0;
                    sc2[row * HH + ucol + 1] = c1;
                    float h0 = sigm(C2g[3][m][e]   + bo0) * tanhf(c0);
                    float h1 = sigm(C2g[3][m][e+1] + bo1) * tanhf(c1);
                    splitStore2(h0, h1, aHi, aLo, row * ASTR + C_H2 + ucol);
                }
        }
        __syncthreads();

        // ===== Phase E: fc1 (1 ntile x 2 mtiles per warp) + tanh -> o3 =====
        {
            float Cf[2][4];
#pragma unroll
            for (int m = 0; m < 2; m++)
#pragma unroll
                for (int e = 0; e < 4; e++) Cf[m][e] = 0.0f;
#pragma unroll 1
            for (int ks = 0; ks < KS3; ks++) {
                u32 Ah0[4], Al0[4], Ah1[4], Al1[4];
                ldm_x4(Ah0, aHiB0 + (u32)(C_H2 * 2 + ks * 32));
                ldm_x4(Al0, aLoB0 + (u32)(C_H2 * 2 + ks * 32));
                ldm_x4(Ah1, aHiB1 + (u32)(C_H2 * 2 + ks * 32));
                ldm_x4(Al1, aLoB1 + (u32)(C_H2 * 2 + ks * 32));
                uint4 b = __ldg(&g_B3[(warp * KS3 + ks) * 32 + lane]);
                mma_bf16(Cf[0], Ah0, b.x, b.y);
                mma_bf16(Cf[0], Ah0, b.z, b.w);
                mma_bf16(Cf[0], Al0, b.x, b.y);
                mma_bf16(Cf[1], Ah1, b.x, b.y);
                mma_bf16(Cf[1], Ah1, b.z, b.w);
                mma_bf16(Cf[1], Al1, b.x, b.y);
            }
            float bb0 = __ldg(&fc1b[ucol]), bb1 = __ldg(&fc1b[ucol + 1]);
#pragma unroll
            for (int m = 0; m < 2; m++)
#pragma unroll
                for (int e2 = 0; e2 < 2; e2++) {
                    int row = crow + 8 * e2 + 16 * m;
                    int e = e2 * 2;
                    splitStore2(tanhf(Cf[m][e] + bb0), tanhf(Cf[m][e + 1] + bb1),
                                aHi, aLo, row * ASTR + C_O3 + ucol);
                }
        }
        __syncthreads();

        // ===== Phase G: fc2 + output + next-step staging =====
        if (warp < 12) {
            int nt = warp % NT4, mt = warp / NT4;
            float C[4];
#pragma unroll
            for (int e = 0; e < 4; e++) C[e] = 0.0f;
            const u32 aH = mt ? aHiB1 : aHiB0;
            const u32 aL = mt ? aLoB1 : aLoB0;
#pragma unroll 1
            for (int ks = 0; ks < KS4; ks++) {
                u32 Ah[4], Al[4];
                ldm_x4(Ah, aH + (u32)(C_O3 * 2 + ks * 32));
                ldm_x4(Al, aL + (u32)(C_O3 * 2 + ks * 32));
                uint4 b = __ldg(&g_B4[(nt * KS4 + ks) * 32 + lane]);
                mma_bf16(C, Ah, b.x, b.y);
                mma_bf16(C, Ah, b.z, b.w);
                mma_bf16(C, Al, b.x, b.y);
            }
            int col = nt * 8 + ccol;
            int r0 = crow + 16 * mt, r1 = crow + 8 + 16 * mt;
            float bb0 = __ldg(&fc2b[col]), bb1 = __ldg(&fc2b[col + 1]);
            float v00 = tanhf(C[0] + bb0), v01 = tanhf(C[1] + bb1);
            float v10 = tanhf(C[2] + bb0), v11 = tanhf(C[3] + bb1);
            if (t >= 9) {
                *(float2*)&out[((size_t)(t - 9) * BB + row0 + r0) * FF + col] = make_float2(v00, v01);
                *(float2*)&out[((size_t)(t - 9) * BB + row0 + r1) * FF + col] = make_float2(v10, v11);
            }
            float n00 = v00, n01 = v01, n10 = v10, n11 = v11;
            if (t + 1 <= 9) {
                const float* tp0 = &tactiles[((size_t)(t + 1) * BB + row0 + r0) * FF + col];
                const float* tp1 = &tactiles[((size_t)(t + 1) * BB + row0 + r1) * FF + col];
                n00 = tp0[0]; n01 = tp0[1]; n10 = tp1[0]; n11 = tp1[1];
            }
            splitStore2(n00, n01, aHi, aLo, r0 * ASTR + C_INP + col);
            splitStore2(n10, n11, aHi, aLo, r1 * ASTR + C_INP + col);
            splitStore2(n00, n01, aHi, aLo, r0 * ASTR + C_INP2 + col);
            splitStore2(n10, n11, aHi, aLo, r1 * ASTR + C_INP2 + col);
        } else {
            // stage til action part for step t+1
            int i2 = tid - 384;
            if (i2 < RRW * 6 && t + 1 < NSTEP) {
                int r = i2 / 6, c = i2 % 6;
                float v = actions[((size_t)(t + 2) * BB + row0 + r) * AA + c];
                splitStore(v, aHi, aLo, r * ASTR + C_TIL + c);
            }
        }
        __syncthreads();
    }
}

// ---------------- launch ----------------
extern "C" void kernel_launch(void* const* d_in, const int* in_sizes, int n_in,
                              void* d_out, int out_size)
{
    (void)in_sizes; (void)n_in; (void)out_size;
    const float* tactiles = (const float*)d_in[0];
    const float* actions  = (const float*)d_in[1];
    const float* W_ih1    = (const float*)d_in[2];
    const float* W_hh1    = (const float*)d_in[3];
    const float* b_ih1    = (const float*)d_in[4];
    const float* b_hh1    = (const float*)d_in[5];
    const float* W_ih2    = (const float*)d_in[6];
    const float* W_hh2    = (const float*)d_in[7];
    const float* b_ih2    = (const float*)d_in[8];
    const float* b_hh2    = (const float*)d_in[9];
    const float* fc1_w    = (const float*)d_in[10];
    const float* fc1_b    = (const float*)d_in[11];
    const float* fc2_w    = (const float*)d_in[12];
    const float* fc2_b    = (const float*)d_in[13];
    float* out = (float*)d_out;

    prep_kernel<<<1024, 256>>>(W_ih1, W_hh1, b_ih1, b_hh1,
                               W_ih2, W_hh2, b_ih2, b_hh2,
                               fc1_w, fc2_w);

    size_t smem_bytes = (size_t)(2 * RRW * ASTR * 2)      // hi/lo arena
                      + (size_t)(2 * RRW * HH * 4);       // c-state (2 layers)
    cudaFuncSetAttribute(actp_main, cudaFuncAttributeMaxDynamicSharedMemorySize, (int)smem_bytes);

    actp_main<<<NCTA, NTHREADS, smem_bytes>>>(tactiles, actions, fc1_b, fc2_b, out);
}